// round 7
// baseline (speedup 1.0000x reference)
#include <cuda_runtime.h>
#include <math.h>

#define EPS 1e-8f
#define MAX_NODES 1048576
#define WPB 8   // warps per block

// 32MB padded node scratch: row i -> g_nodes8[2i] = {t.x,t.y,t.z,q.x}, g_nodes8[2i+1] = {q.y,q.z,q.w,pad}
__device__ float4 g_nodes8[(size_t)MAX_NODES * 2];

struct V3 { float x, y, z; };
struct Q4 { float x, y, z, w; };

__device__ __forceinline__ V3 v3(float x, float y, float z) { V3 r; r.x=x; r.y=y; r.z=z; return r; }
__device__ __forceinline__ V3 vadd(V3 a, V3 b) { return v3(a.x+b.x, a.y+b.y, a.z+b.z); }
__device__ __forceinline__ V3 vsub(V3 a, V3 b) { return v3(a.x-b.x, a.y-b.y, a.z-b.z); }
__device__ __forceinline__ V3 vscale(V3 a, float s) { return v3(a.x*s, a.y*s, a.z*s); }
__device__ __forceinline__ float vdot(V3 a, V3 b) { return fmaf(a.x,b.x, fmaf(a.y,b.y, a.z*b.z)); }
__device__ __forceinline__ V3 vcross(V3 a, V3 b) {
    return v3(a.y*b.z - a.z*b.y,
              a.z*b.x - a.x*b.z,
              a.x*b.y - a.y*b.x);
}

__device__ __forceinline__ Q4 qconj(Q4 q) { Q4 r; r.x=-q.x; r.y=-q.y; r.z=-q.z; r.w=q.w; return r; }

__device__ __forceinline__ Q4 qmul(Q4 q, Q4 r) {
    Q4 o;
    V3 qv = v3(q.x,q.y,q.z), rv = v3(r.x,r.y,r.z);
    V3 c = vcross(qv, rv);
    o.x = q.w*r.x + r.w*q.x + c.x;
    o.y = q.w*r.y + r.w*q.y + c.y;
    o.z = q.w*r.z + r.w*q.z + c.z;
    o.w = q.w*r.w - vdot(qv, rv);
    return o;
}

__device__ __forceinline__ V3 qrot(Q4 q, V3 v) {
    V3 qv = v3(q.x,q.y,q.z);
    V3 t = vscale(vcross(qv, v), 2.0f);
    return vadd(vadd(v, vscale(t, q.w)), vcross(qv, t));
}

__device__ __forceinline__ V3 so3_log(Q4 q) {
    V3 v = v3(q.x,q.y,q.z);
    float n2 = vdot(v, v);
    float n = sqrtf(n2);
    float theta = 2.0f * atan2f(n, q.w);
    float k;
    if (n > EPS) {
        k = theta / n;
    } else {
        float wd = (fabsf(q.w) > EPS) ? q.w : 1.0f;
        k = 2.0f / wd;
    }
    return vscale(v, k);
}

__device__ __forceinline__ void se3_log(V3 t, Q4 q, V3* tau, V3* phi_out) {
    V3 phi = so3_log(q);
    float theta2 = vdot(phi, phi);
    float theta = sqrtf(theta2);
    float coef;
    if (theta < 1e-4f) {
        coef = 1.0f / 12.0f;
    } else {
        float s, c;
        sincosf(theta, &s, &c);
        coef = 1.0f / theta2 - (1.0f + c) / (2.0f * theta * s);
    }
    V3 pxt = vcross(phi, t);
    *tau = vadd(vsub(t, vscale(pxt, 0.5f)), vscale(vcross(phi, pxt), coef));
    *phi_out = phi;
}

// --- Vectorized 7-float row fetch for CONTIGUOUS streams: 3 aligned float4 (3rd predicated) ---
struct Row12 { float4 r0, r1, r2; int off; };

__device__ __forceinline__ Row12 fetch_row_vec(const float4* __restrict__ p4, size_t row_idx) {
    Row12 r;
    size_t base = row_idx * 7;
    size_t a = base >> 2;
    r.off = (int)(base & 3);
    r.r0 = __ldcs(p4 + a);
    r.r1 = __ldcs(p4 + a + 1);
    r.r2 = (r.off >= 2) ? __ldcs(p4 + a + 2) : r.r1;
    return r;
}

__device__ __forceinline__ void extract7(const Row12& rr, V3* t, Q4* q) {
    float s0=rr.r0.x, s1=rr.r0.y, s2=rr.r0.z, s3=rr.r0.w;
    float s4=rr.r1.x, s5=rr.r1.y, s6=rr.r1.z, s7=rr.r1.w;
    float s8=rr.r2.x, s9=rr.r2.y;
    bool o2 = (rr.off & 2) != 0;
    bool o1 = (rr.off & 1) != 0;
    float u0 = o2 ? s2 : s0;
    float u1 = o2 ? s3 : s1;
    float u2 = o2 ? s4 : s2;
    float u3 = o2 ? s5 : s3;
    float u4 = o2 ? s6 : s4;
    float u5 = o2 ? s7 : s5;
    float u6 = o2 ? s8 : s6;
    float u7 = o2 ? s9 : s7;
    float v0 = o1 ? u1 : u0;
    float v1 = o1 ? u2 : u1;
    float v2 = o1 ? u3 : u2;
    float v3f = o1 ? u4 : u3;
    float v4 = o1 ? u5 : u4;
    float v5 = o1 ? u6 : u5;
    float v6 = o1 ? u7 : u6;
    t->x = v0; t->y = v1; t->z = v2;
    q->x = v3f; q->y = v4; q->z = v5; q->w = v6;
}

__device__ __forceinline__ void fetch_row_scalar(const float* __restrict__ p, size_t row_idx,
                                                 V3* t, Q4* q) {
    const float* r = p + row_idx * 7;
    t->x = __ldcs(r+0); t->y = __ldcs(r+1); t->z = __ldcs(r+2);
    q->x = __ldcs(r+3); q->y = __ldcs(r+4); q->z = __ldcs(r+5); q->w = __ldcs(r+6);
}

// --- Prep kernel: repack nodes into scratch AND compute node residuals ---
template<bool VEC>
__global__ __launch_bounds__(256)
void prep_kernel(const float* __restrict__ nodes,
                 const float* __restrict__ vels,
                 const float* __restrict__ imu_drots,
                 const float* __restrict__ imu_dtrans,
                 const float* __restrict__ imu_dvels,
                 const float* __restrict__ dts,
                 float* __restrict__ out_adjvel,
                 float* __restrict__ out_imurot,
                 float* __restrict__ out_transvel,
                 int N, int M)
{
    int i = blockIdx.x * blockDim.x + threadIdx.x;
    int lane = threadIdx.x & 31;
    bool v_row = i < N;
    int ic = v_row ? i : (N - 1);

    V3 t0; Q4 q0;
    if (VEC) {
        Row12 r = fetch_row_vec(reinterpret_cast<const float4*>(nodes), (size_t)ic);
        extract7(r, &t0, &q0);
    } else {
        fetch_row_scalar(nodes, (size_t)ic, &t0, &q0);
    }

    if (v_row) {
        g_nodes8[2*(size_t)i]     = make_float4(t0.x, t0.y, t0.z, q0.x);
        g_nodes8[2*(size_t)i + 1] = make_float4(q0.y, q0.z, q0.w, 0.0f);
    }

    float v0x = __ldcs(vels + 3*(size_t)ic + 0);
    float v0y = __ldcs(vels + 3*(size_t)ic + 1);
    float v0z = __ldcs(vels + 3*(size_t)ic + 2);

    unsigned mask = 0xffffffffu;
    V3 t1; Q4 q1;
    t1.x = __shfl_down_sync(mask, t0.x, 1);
    t1.y = __shfl_down_sync(mask, t0.y, 1);
    t1.z = __shfl_down_sync(mask, t0.z, 1);
    q1.x = __shfl_down_sync(mask, q0.x, 1);
    q1.y = __shfl_down_sync(mask, q0.y, 1);
    q1.z = __shfl_down_sync(mask, q0.z, 1);
    q1.w = __shfl_down_sync(mask, q0.w, 1);
    float v1x = __shfl_down_sync(mask, v0x, 1);
    float v1y = __shfl_down_sync(mask, v0y, 1);
    float v1z = __shfl_down_sync(mask, v0z, 1);

    if (i >= M) return;

    if (lane == 31) {
        if (VEC) {
            Row12 r = fetch_row_vec(reinterpret_cast<const float4*>(nodes), (size_t)(i+1));
            extract7(r, &t1, &q1);
        } else {
            fetch_row_scalar(nodes, (size_t)(i+1), &t1, &q1);
        }
        v1x = __ldcs(vels + 3*(size_t)(i+1) + 0);
        v1y = __ldcs(vels + 3*(size_t)(i+1) + 1);
        v1z = __ldcs(vels + 3*(size_t)(i+1) + 2);
    }

    float4 drq = __ldcs(reinterpret_cast<const float4*>(imu_drots) + i);
    float dvx = __ldcs(imu_dvels + 3*(size_t)i + 0);
    float dvy = __ldcs(imu_dvels + 3*(size_t)i + 1);
    float dvz = __ldcs(imu_dvels + 3*(size_t)i + 2);
    float dtx = __ldcs(imu_dtrans + 3*(size_t)i + 0);
    float dty = __ldcs(imu_dtrans + 3*(size_t)i + 1);
    float dtz = __ldcs(imu_dtrans + 3*(size_t)i + 2);
    float dt  = __ldcs(dts + i);

    __stcs(out_adjvel + 3*(size_t)i + 0, 0.1f * (dvx - (v1x - v0x)));
    __stcs(out_adjvel + 3*(size_t)i + 1, 0.1f * (dvy - (v1y - v0y)));
    __stcs(out_adjvel + 3*(size_t)i + 2, 0.1f * (dvz - (v1z - v0z)));

    Q4 dr; dr.x=drq.x; dr.y=drq.y; dr.z=drq.z; dr.w=drq.w;
    Q4 qre = qmul(qconj(dr), qmul(qconj(q0), q1));
    V3 rot = so3_log(qre);
    __stcs(out_imurot + 3*(size_t)i + 0, rot.x);
    __stcs(out_imurot + 3*(size_t)i + 1, rot.y);
    __stcs(out_imurot + 3*(size_t)i + 2, rot.z);

    __stcs(out_transvel + 3*(size_t)i + 0, 0.1f * (t1.x - t0.x - fmaf(v0x, dt, dtx)));
    __stcs(out_transvel + 3*(size_t)i + 1, 0.1f * (t1.y - t0.y - fmaf(v0y, dt, dty)));
    __stcs(out_transvel + 3*(size_t)i + 2, 0.1f * (t1.z - t0.z - fmaf(v0z, dt, dtz)));
}

// --- Edge kernel: paired-lane cooperative gather through swizzled smem ---
// Per warp: 64 scratch rows (n1[0..31], n2[0..31]) = 128 float4 slots.
// Logical float4 index f = 2*row + part; physical slot = f ^ ((f>>3)&7).
// Gather: lanes 2k/2k+1 fetch part0/part1 of the same row -> each LDG.128
// instruction touches only 16 distinct 128B lines (rows are 32B aligned).
template<bool VEC>
__global__ __launch_bounds__(256)
void edge_kernel(const int*   __restrict__ edges,
                 const float* __restrict__ poses,
                 float* __restrict__ out_pg,
                 int E)
{
    __shared__ float4 sm[WPB][128];

    int lane = threadIdx.x & 31;
    int wib  = threadIdx.x >> 5;
    int e = blockIdx.x * blockDim.x + threadIdx.x;
    int e_base = e - lane;
    if (e_base >= E) return;
    bool valid = e < E;
    int ecl = valid ? e : (E - 1);

    int2 id = __ldcs(reinterpret_cast<const int2*>(edges) + ecl);

    float4* ws = sm[wib];
    int part  = lane & 1;
    int rbase = lane >> 1;

    #pragma unroll
    for (int p = 0; p < 4; p++) {
        int r = p * 16 + rbase;             // row slot 0..63
        int src = r & 31;                   // owning lane for this row's index
        int ni = (r < 32) ? __shfl_sync(0xffffffffu, id.x, src)
                          : __shfl_sync(0xffffffffu, id.y, src);
        int f = (r << 1) | part;            // logical float4 index
        int phys = f ^ ((f >> 3) & 7);      // bank-group swizzle
        ws[phys] = __ldg(&g_nodes8[2 * (size_t)ni + part]);
    }
    __syncwarp();

    V3 t1, t2, tp;
    Q4 q1, q2, qp;
    {
        int f0 = lane << 1;                 // n1 row = lane
        int pa = f0 ^ ((f0 >> 3) & 7);
        float4 a = ws[pa];
        float4 b = ws[pa ^ 1];
        t1.x=a.x; t1.y=a.y; t1.z=a.z;
        q1.x=a.w; q1.y=b.x; q1.z=b.y; q1.w=b.z;
    }
    {
        int f0 = (32 + lane) << 1;          // n2 row = 32+lane
        int pa = f0 ^ ((f0 >> 3) & 7);
        float4 a = ws[pa];
        float4 b = ws[pa ^ 1];
        t2.x=a.x; t2.y=a.y; t2.z=a.z;
        q2.x=a.w; q2.y=b.x; q2.z=b.y; q2.w=b.z;
    }

    if (VEC) {
        Row12 rp = fetch_row_vec(reinterpret_cast<const float4*>(poses), (size_t)ecl);
        extract7(rp, &tp, &qp);
    } else {
        fetch_row_scalar(poses, (size_t)ecl, &tp, &qp);
    }

    Q4 qi1 = qconj(q1);
    V3 ti1 = vscale(qrot(qi1, t1), -1.0f);
    Q4 qa  = qmul(qi1, q2);
    V3 ta  = vadd(ti1, qrot(qi1, t2));

    Q4 qip = qconj(qp);
    V3 tip = vscale(qrot(qip, tp), -1.0f);
    Q4 qe  = qmul(qip, qa);
    V3 te  = vadd(tip, qrot(qip, ta));

    V3 tau, phi;
    se3_log(te, qe, &tau, &phi);

    if (valid) {
        float2* o2 = reinterpret_cast<float2*>(out_pg + 6*(size_t)e);
        __stcs(o2 + 0, make_float2(tau.x, tau.y));
        __stcs(o2 + 1, make_float2(tau.z, phi.x));
        __stcs(o2 + 2, make_float2(phi.y, phi.z));
    }
}

// --- Fallback: edge path reading nodes directly (N > MAX_NODES) ---
__global__ __launch_bounds__(256)
void edge_fallback_kernel(const int*   __restrict__ edges,
                          const float* __restrict__ nodes,
                          const float* __restrict__ poses,
                          float* __restrict__ out_pg,
                          int E)
{
    int e = blockIdx.x * blockDim.x + threadIdx.x;
    if (e >= E) return;
    int2 id = __ldcs(reinterpret_cast<const int2*>(edges) + e);
    V3 t1, t2, tp; Q4 q1, q2, qp;
    fetch_row_scalar(nodes, (size_t)id.x, &t1, &q1);
    fetch_row_scalar(nodes, (size_t)id.y, &t2, &q2);
    fetch_row_scalar(poses, (size_t)e,    &tp, &qp);

    Q4 qi1 = qconj(q1);
    V3 ti1 = vscale(qrot(qi1, t1), -1.0f);
    Q4 qa  = qmul(qi1, q2);
    V3 ta  = vadd(ti1, qrot(qi1, t2));
    Q4 qip = qconj(qp);
    V3 tip = vscale(qrot(qip, tp), -1.0f);
    Q4 qe  = qmul(qip, qa);
    V3 te  = vadd(tip, qrot(qip, ta));
    V3 tau, phi;
    se3_log(te, qe, &tau, &phi);

    float* o = out_pg + 6*(size_t)e;
    o[0]=tau.x; o[1]=tau.y; o[2]=tau.z; o[3]=phi.x; o[4]=phi.y; o[5]=phi.z;
}

extern "C" void kernel_launch(void* const* d_in, const int* in_sizes, int n_in,
                              void* d_out, int out_size) {
    const int*   edges      = (const int*)  d_in[0];
    const float* nodes      = (const float*)d_in[1];
    const float* vels       = (const float*)d_in[2];
    const float* poses      = (const float*)d_in[3];
    const float* imu_drots  = (const float*)d_in[4];
    const float* imu_dtrans = (const float*)d_in[5];
    const float* imu_dvels  = (const float*)d_in[6];
    const float* dts        = (const float*)d_in[7];

    int E = in_sizes[0] / 2;
    int N = in_sizes[1] / 7;
    int M = N - 1;

    float* out = (float*)d_out;
    float* out_pg       = out;
    float* out_adjvel   = out + (size_t)6 * E;
    float* out_imurot   = out_adjvel + (size_t)3 * M;
    float* out_transvel = out_imurot + (size_t)3 * M;

    const int TPB = 256;
    int prepBlocks = (N + TPB - 1) / TPB;
    int edgeBlocks = (E + TPB - 1) / TPB;

    bool nodes_vec_ok = ((in_sizes[1] & 3) == 0);
    bool poses_vec_ok = ((in_sizes[3] & 3) == 0);
    bool scr_ok = (N <= MAX_NODES);

    if (scr_ok) {
        if (nodes_vec_ok) {
            prep_kernel<true><<<prepBlocks, TPB>>>(nodes, vels, imu_drots, imu_dtrans,
                                                   imu_dvels, dts,
                                                   out_adjvel, out_imurot, out_transvel, N, M);
        } else {
            prep_kernel<false><<<prepBlocks, TPB>>>(nodes, vels, imu_drots, imu_dtrans,
                                                    imu_dvels, dts,
                                                    out_adjvel, out_imurot, out_transvel, N, M);
        }
        if (poses_vec_ok) {
            edge_kernel<true><<<edgeBlocks, TPB>>>(edges, poses, out_pg, E);
        } else {
            edge_kernel<false><<<edgeBlocks, TPB>>>(edges, poses, out_pg, E);
        }
    } else {
        prep_kernel<false><<<prepBlocks, TPB>>>(nodes, vels, imu_drots, imu_dtrans,
                                                imu_dvels, dts,
                                                out_adjvel, out_imurot, out_transvel,
                                                0, M);
        edge_fallback_kernel<<<edgeBlocks, TPB>>>(edges, nodes, poses, out_pg, E);
    }
}

// round 8
// speedup vs baseline: 1.0412x; 1.0412x over previous
#include <cuda_runtime.h>
#include <math.h>

#define EPS 1e-8f
#define MAX_NODES 1048576

// 32MB padded node scratch: row i -> g_nodes8[2i] = {t.x,t.y,t.z,q.x}, g_nodes8[2i+1] = {q.y,q.z,q.w,pad}
// Rows are 32B-aligned -> one ld.global.v8 per row.
__device__ __align__(32) float4 g_nodes8[(size_t)MAX_NODES * 2];

struct V3 { float x, y, z; };
struct Q4 { float x, y, z, w; };

__device__ __forceinline__ V3 v3(float x, float y, float z) { V3 r; r.x=x; r.y=y; r.z=z; return r; }
__device__ __forceinline__ V3 vadd(V3 a, V3 b) { return v3(a.x+b.x, a.y+b.y, a.z+b.z); }
__device__ __forceinline__ V3 vsub(V3 a, V3 b) { return v3(a.x-b.x, a.y-b.y, a.z-b.z); }
__device__ __forceinline__ V3 vscale(V3 a, float s) { return v3(a.x*s, a.y*s, a.z*s); }
__device__ __forceinline__ float vdot(V3 a, V3 b) { return fmaf(a.x,b.x, fmaf(a.y,b.y, a.z*b.z)); }
__device__ __forceinline__ V3 vcross(V3 a, V3 b) {
    return v3(a.y*b.z - a.z*b.y,
              a.z*b.x - a.x*b.z,
              a.x*b.y - a.y*b.x);
}

__device__ __forceinline__ Q4 qconj(Q4 q) { Q4 r; r.x=-q.x; r.y=-q.y; r.z=-q.z; r.w=q.w; return r; }

__device__ __forceinline__ Q4 qmul(Q4 q, Q4 r) {
    Q4 o;
    V3 qv = v3(q.x,q.y,q.z), rv = v3(r.x,r.y,r.z);
    V3 c = vcross(qv, rv);
    o.x = q.w*r.x + r.w*q.x + c.x;
    o.y = q.w*r.y + r.w*q.y + c.y;
    o.z = q.w*r.z + r.w*q.z + c.z;
    o.w = q.w*r.w - vdot(qv, rv);
    return o;
}

__device__ __forceinline__ V3 qrot(Q4 q, V3 v) {
    V3 qv = v3(q.x,q.y,q.z);
    V3 t = vscale(vcross(qv, v), 2.0f);
    return vadd(vadd(v, vscale(t, q.w)), vcross(qv, t));
}

__device__ __forceinline__ V3 so3_log(Q4 q) {
    V3 v = v3(q.x,q.y,q.z);
    float n2 = vdot(v, v);
    float n = sqrtf(n2);
    float theta = 2.0f * atan2f(n, q.w);
    float k;
    if (n > EPS) {
        k = theta / n;
    } else {
        float wd = (fabsf(q.w) > EPS) ? q.w : 1.0f;
        k = 2.0f / wd;
    }
    return vscale(v, k);
}

__device__ __forceinline__ void se3_log(V3 t, Q4 q, V3* tau, V3* phi_out) {
    V3 phi = so3_log(q);
    float theta2 = vdot(phi, phi);
    float theta = sqrtf(theta2);
    float coef;
    if (theta < 1e-4f) {
        coef = 1.0f / 12.0f;
    } else {
        float s, c;
        sincosf(theta, &s, &c);
        coef = 1.0f / theta2 - (1.0f + c) / (2.0f * theta * s);
    }
    V3 pxt = vcross(phi, t);
    *tau = vadd(vsub(t, vscale(pxt, 0.5f)), vscale(vcross(phi, pxt), coef));
    *phi_out = phi;
}

// --- Vectorized 7-float row fetch for CONTIGUOUS streams: 3 aligned float4 (3rd predicated) ---
struct Row12 { float4 r0, r1, r2; int off; };

__device__ __forceinline__ Row12 fetch_row_vec(const float4* __restrict__ p4, size_t row_idx) {
    Row12 r;
    size_t base = row_idx * 7;
    size_t a = base >> 2;
    r.off = (int)(base & 3);
    r.r0 = __ldcs(p4 + a);
    r.r1 = __ldcs(p4 + a + 1);
    r.r2 = (r.off >= 2) ? __ldcs(p4 + a + 2) : r.r1;
    return r;
}

__device__ __forceinline__ void extract7(const Row12& rr, V3* t, Q4* q) {
    float s0=rr.r0.x, s1=rr.r0.y, s2=rr.r0.z, s3=rr.r0.w;
    float s4=rr.r1.x, s5=rr.r1.y, s6=rr.r1.z, s7=rr.r1.w;
    float s8=rr.r2.x, s9=rr.r2.y;
    bool o2 = (rr.off & 2) != 0;
    bool o1 = (rr.off & 1) != 0;
    float u0 = o2 ? s2 : s0;
    float u1 = o2 ? s3 : s1;
    float u2 = o2 ? s4 : s2;
    float u3 = o2 ? s5 : s3;
    float u4 = o2 ? s6 : s4;
    float u5 = o2 ? s7 : s5;
    float u6 = o2 ? s8 : s6;
    float u7 = o2 ? s9 : s7;
    float v0 = o1 ? u1 : u0;
    float v1 = o1 ? u2 : u1;
    float v2 = o1 ? u3 : u2;
    float v3f = o1 ? u4 : u3;
    float v4 = o1 ? u5 : u4;
    float v5 = o1 ? u6 : u5;
    float v6 = o1 ? u7 : u6;
    t->x = v0; t->y = v1; t->z = v2;
    q->x = v3f; q->y = v4; q->z = v5; q->w = v6;
}

__device__ __forceinline__ void fetch_row_scalar(const float* __restrict__ p, size_t row_idx,
                                                 V3* t, Q4* q) {
    const float* r = p + row_idx * 7;
    t->x = __ldcs(r+0); t->y = __ldcs(r+1); t->z = __ldcs(r+2);
    q->x = __ldcs(r+3); q->y = __ldcs(r+4); q->z = __ldcs(r+5); q->w = __ldcs(r+6);
}

// --- 256-bit single-instruction row gather (sm_100+: ld.global.nc.v8.b32) ---
__device__ __forceinline__ void load_row8_v8(size_t i, V3* t, Q4* q) {
    const float4* p = &g_nodes8[2 * i];
    unsigned r0, r1, r2, r3, r4, r5, r6, r7;
    asm volatile("ld.global.nc.v8.b32 {%0,%1,%2,%3,%4,%5,%6,%7}, [%8];"
                 : "=r"(r0), "=r"(r1), "=r"(r2), "=r"(r3),
                   "=r"(r4), "=r"(r5), "=r"(r6), "=r"(r7)
                 : "l"(p));
    t->x = __uint_as_float(r0);
    t->y = __uint_as_float(r1);
    t->z = __uint_as_float(r2);
    q->x = __uint_as_float(r3);
    q->y = __uint_as_float(r4);
    q->z = __uint_as_float(r5);
    q->w = __uint_as_float(r6);
}

// --- Prep kernel: repack nodes into scratch AND compute node residuals ---
template<bool VEC>
__global__ __launch_bounds__(256)
void prep_kernel(const float* __restrict__ nodes,
                 const float* __restrict__ vels,
                 const float* __restrict__ imu_drots,
                 const float* __restrict__ imu_dtrans,
                 const float* __restrict__ imu_dvels,
                 const float* __restrict__ dts,
                 float* __restrict__ out_adjvel,
                 float* __restrict__ out_imurot,
                 float* __restrict__ out_transvel,
                 int N, int M)
{
    int i = blockIdx.x * blockDim.x + threadIdx.x;
    int lane = threadIdx.x & 31;
    bool v_row = i < N;
    int ic = v_row ? i : (N - 1);

    V3 t0; Q4 q0;
    if (VEC) {
        Row12 r = fetch_row_vec(reinterpret_cast<const float4*>(nodes), (size_t)ic);
        extract7(r, &t0, &q0);
    } else {
        fetch_row_scalar(nodes, (size_t)ic, &t0, &q0);
    }

    if (v_row) {
        g_nodes8[2*(size_t)i]     = make_float4(t0.x, t0.y, t0.z, q0.x);
        g_nodes8[2*(size_t)i + 1] = make_float4(q0.y, q0.z, q0.w, 0.0f);
    }

    float v0x = __ldcs(vels + 3*(size_t)ic + 0);
    float v0y = __ldcs(vels + 3*(size_t)ic + 1);
    float v0z = __ldcs(vels + 3*(size_t)ic + 2);

    unsigned mask = 0xffffffffu;
    V3 t1; Q4 q1;
    t1.x = __shfl_down_sync(mask, t0.x, 1);
    t1.y = __shfl_down_sync(mask, t0.y, 1);
    t1.z = __shfl_down_sync(mask, t0.z, 1);
    q1.x = __shfl_down_sync(mask, q0.x, 1);
    q1.y = __shfl_down_sync(mask, q0.y, 1);
    q1.z = __shfl_down_sync(mask, q0.z, 1);
    q1.w = __shfl_down_sync(mask, q0.w, 1);
    float v1x = __shfl_down_sync(mask, v0x, 1);
    float v1y = __shfl_down_sync(mask, v0y, 1);
    float v1z = __shfl_down_sync(mask, v0z, 1);

    if (i >= M) return;

    if (lane == 31) {
        if (VEC) {
            Row12 r = fetch_row_vec(reinterpret_cast<const float4*>(nodes), (size_t)(i+1));
            extract7(r, &t1, &q1);
        } else {
            fetch_row_scalar(nodes, (size_t)(i+1), &t1, &q1);
        }
        v1x = __ldcs(vels + 3*(size_t)(i+1) + 0);
        v1y = __ldcs(vels + 3*(size_t)(i+1) + 1);
        v1z = __ldcs(vels + 3*(size_t)(i+1) + 2);
    }

    float4 drq = __ldcs(reinterpret_cast<const float4*>(imu_drots) + i);
    float dvx = __ldcs(imu_dvels + 3*(size_t)i + 0);
    float dvy = __ldcs(imu_dvels + 3*(size_t)i + 1);
    float dvz = __ldcs(imu_dvels + 3*(size_t)i + 2);
    float dtx = __ldcs(imu_dtrans + 3*(size_t)i + 0);
    float dty = __ldcs(imu_dtrans + 3*(size_t)i + 1);
    float dtz = __ldcs(imu_dtrans + 3*(size_t)i + 2);
    float dt  = __ldcs(dts + i);

    __stcs(out_adjvel + 3*(size_t)i + 0, 0.1f * (dvx - (v1x - v0x)));
    __stcs(out_adjvel + 3*(size_t)i + 1, 0.1f * (dvy - (v1y - v0y)));
    __stcs(out_adjvel + 3*(size_t)i + 2, 0.1f * (dvz - (v1z - v0z)));

    Q4 dr; dr.x=drq.x; dr.y=drq.y; dr.z=drq.z; dr.w=drq.w;
    Q4 qre = qmul(qconj(dr), qmul(qconj(q0), q1));
    V3 rot = so3_log(qre);
    __stcs(out_imurot + 3*(size_t)i + 0, rot.x);
    __stcs(out_imurot + 3*(size_t)i + 1, rot.y);
    __stcs(out_imurot + 3*(size_t)i + 2, rot.z);

    __stcs(out_transvel + 3*(size_t)i + 0, 0.1f * (t1.x - t0.x - fmaf(v0x, dt, dtx)));
    __stcs(out_transvel + 3*(size_t)i + 1, 0.1f * (t1.y - t0.y - fmaf(v0y, dt, dty)));
    __stcs(out_transvel + 3*(size_t)i + 2, 0.1f * (t1.z - t0.z - fmaf(v0z, dt, dtz)));
}

// --- Edge kernel: pose-graph residual, 256-bit row gathers ---
template<bool VEC>
__global__ __launch_bounds__(256)
void edge_kernel(const int*   __restrict__ edges,
                 const float* __restrict__ poses,
                 float* __restrict__ out_pg,
                 int E)
{
    int e = blockIdx.x * blockDim.x + threadIdx.x;
    if (e >= E) return;

    int2 id = __ldcs(reinterpret_cast<const int2*>(edges) + e);

    V3 t1, t2, tp;
    Q4 q1, q2, qp;
    load_row8_v8((size_t)id.x, &t1, &q1);
    load_row8_v8((size_t)id.y, &t2, &q2);

    if (VEC) {
        Row12 rp = fetch_row_vec(reinterpret_cast<const float4*>(poses), (size_t)e);
        extract7(rp, &tp, &qp);
    } else {
        fetch_row_scalar(poses, (size_t)e, &tp, &qp);
    }

    Q4 qi1 = qconj(q1);
    V3 ti1 = vscale(qrot(qi1, t1), -1.0f);
    Q4 qa  = qmul(qi1, q2);
    V3 ta  = vadd(ti1, qrot(qi1, t2));

    Q4 qip = qconj(qp);
    V3 tip = vscale(qrot(qip, tp), -1.0f);
    Q4 qe  = qmul(qip, qa);
    V3 te  = vadd(tip, qrot(qip, ta));

    V3 tau, phi;
    se3_log(te, qe, &tau, &phi);

    // 24B per edge, 8-aligned: 3x STG.64 streaming stores
    float2* o2 = reinterpret_cast<float2*>(out_pg + 6*(size_t)e);
    __stcs(o2 + 0, make_float2(tau.x, tau.y));
    __stcs(o2 + 1, make_float2(tau.z, phi.x));
    __stcs(o2 + 2, make_float2(phi.y, phi.z));
}

// --- Fallback: edge path reading nodes directly (N > MAX_NODES) ---
__global__ __launch_bounds__(256)
void edge_fallback_kernel(const int*   __restrict__ edges,
                          const float* __restrict__ nodes,
                          const float* __restrict__ poses,
                          float* __restrict__ out_pg,
                          int E)
{
    int e = blockIdx.x * blockDim.x + threadIdx.x;
    if (e >= E) return;
    int2 id = __ldcs(reinterpret_cast<const int2*>(edges) + e);
    V3 t1, t2, tp; Q4 q1, q2, qp;
    fetch_row_scalar(nodes, (size_t)id.x, &t1, &q1);
    fetch_row_scalar(nodes, (size_t)id.y, &t2, &q2);
    fetch_row_scalar(poses, (size_t)e,    &tp, &qp);

    Q4 qi1 = qconj(q1);
    V3 ti1 = vscale(qrot(qi1, t1), -1.0f);
    Q4 qa  = qmul(qi1, q2);
    V3 ta  = vadd(ti1, qrot(qi1, t2));
    Q4 qip = qconj(qp);
    V3 tip = vscale(qrot(qip, tp), -1.0f);
    Q4 qe  = qmul(qip, qa);
    V3 te  = vadd(tip, qrot(qip, ta));
    V3 tau, phi;
    se3_log(te, qe, &tau, &phi);

    float* o = out_pg + 6*(size_t)e;
    o[0]=tau.x; o[1]=tau.y; o[2]=tau.z; o[3]=phi.x; o[4]=phi.y; o[5]=phi.z;
}

extern "C" void kernel_launch(void* const* d_in, const int* in_sizes, int n_in,
                              void* d_out, int out_size) {
    const int*   edges      = (const int*)  d_in[0];
    const float* nodes      = (const float*)d_in[1];
    const float* vels       = (const float*)d_in[2];
    const float* poses      = (const float*)d_in[3];
    const float* imu_drots  = (const float*)d_in[4];
    const float* imu_dtrans = (const float*)d_in[5];
    const float* imu_dvels  = (const float*)d_in[6];
    const float* dts        = (const float*)d_in[7];

    int E = in_sizes[0] / 2;
    int N = in_sizes[1] / 7;
    int M = N - 1;

    float* out = (float*)d_out;
    float* out_pg       = out;
    float* out_adjvel   = out + (size_t)6 * E;
    float* out_imurot   = out_adjvel + (size_t)3 * M;
    float* out_transvel = out_imurot + (size_t)3 * M;

    const int TPB = 256;
    int prepBlocks = (N + TPB - 1) / TPB;
    int edgeBlocks = (E + TPB - 1) / TPB;

    bool nodes_vec_ok = ((in_sizes[1] & 3) == 0);
    bool poses_vec_ok = ((in_sizes[3] & 3) == 0);
    bool scr_ok = (N <= MAX_NODES);

    if (scr_ok) {
        if (nodes_vec_ok) {
            prep_kernel<true><<<prepBlocks, TPB>>>(nodes, vels, imu_drots, imu_dtrans,
                                                   imu_dvels, dts,
                                                   out_adjvel, out_imurot, out_transvel, N, M);
        } else {
            prep_kernel<false><<<prepBlocks, TPB>>>(nodes, vels, imu_drots, imu_dtrans,
                                                    imu_dvels, dts,
                                                    out_adjvel, out_imurot, out_transvel, N, M);
        }
        if (poses_vec_ok) {
            edge_kernel<true><<<edgeBlocks, TPB>>>(edges, poses, out_pg, E);
        } else {
            edge_kernel<false><<<edgeBlocks, TPB>>>(edges, poses, out_pg, E);
        }
    } else {
        prep_kernel<false><<<prepBlocks, TPB>>>(nodes, vels, imu_drots, imu_dtrans,
                                                imu_dvels, dts,
                                                out_adjvel, out_imurot, out_transvel,
                                                0, M);
        edge_fallback_kernel<<<edgeBlocks, TPB>>>(edges, nodes, poses, out_pg, E);
    }
}

// round 9
// speedup vs baseline: 1.0692x; 1.0268x over previous
#include <cuda_runtime.h>
#include <math.h>

#define EPS 1e-8f
#define MAX_NODES 1048576

// 32MB padded node scratch: row i -> g_nodes8[2i] = {t.x,t.y,t.z,q.x}, g_nodes8[2i+1] = {q.y,q.z,q.w,pad}
__device__ __align__(32) float4 g_nodes8[(size_t)MAX_NODES * 2];

struct V3 { float x, y, z; };
struct Q4 { float x, y, z, w; };

__device__ __forceinline__ V3 v3(float x, float y, float z) { V3 r; r.x=x; r.y=y; r.z=z; return r; }
__device__ __forceinline__ V3 vadd(V3 a, V3 b) { return v3(a.x+b.x, a.y+b.y, a.z+b.z); }
__device__ __forceinline__ V3 vsub(V3 a, V3 b) { return v3(a.x-b.x, a.y-b.y, a.z-b.z); }
__device__ __forceinline__ V3 vscale(V3 a, float s) { return v3(a.x*s, a.y*s, a.z*s); }
__device__ __forceinline__ float vdot(V3 a, V3 b) { return fmaf(a.x,b.x, fmaf(a.y,b.y, a.z*b.z)); }
__device__ __forceinline__ V3 vcross(V3 a, V3 b) {
    return v3(a.y*b.z - a.z*b.y,
              a.z*b.x - a.x*b.z,
              a.x*b.y - a.y*b.x);
}

__device__ __forceinline__ Q4 qconj(Q4 q) { Q4 r; r.x=-q.x; r.y=-q.y; r.z=-q.z; r.w=q.w; return r; }

__device__ __forceinline__ Q4 qmul(Q4 q, Q4 r) {
    Q4 o;
    V3 qv = v3(q.x,q.y,q.z), rv = v3(r.x,r.y,r.z);
    V3 c = vcross(qv, rv);
    o.x = q.w*r.x + r.w*q.x + c.x;
    o.y = q.w*r.y + r.w*q.y + c.y;
    o.z = q.w*r.z + r.w*q.z + c.z;
    o.w = q.w*r.w - vdot(qv, rv);
    return o;
}

__device__ __forceinline__ V3 qrot(Q4 q, V3 v) {
    V3 qv = v3(q.x,q.y,q.z);
    V3 t = vscale(vcross(qv, v), 2.0f);
    return vadd(vadd(v, vscale(t, q.w)), vcross(qv, t));
}

__device__ __forceinline__ V3 so3_log(Q4 q) {
    V3 v = v3(q.x,q.y,q.z);
    float n2 = vdot(v, v);
    float n = sqrtf(n2);
    float theta = 2.0f * atan2f(n, q.w);
    float k;
    if (n > EPS) {
        k = theta / n;
    } else {
        float wd = (fabsf(q.w) > EPS) ? q.w : 1.0f;
        k = 2.0f / wd;
    }
    return vscale(v, k);
}

__device__ __forceinline__ void se3_log(V3 t, Q4 q, V3* tau, V3* phi_out) {
    V3 phi = so3_log(q);
    float theta2 = vdot(phi, phi);
    float theta = sqrtf(theta2);
    float coef;
    if (theta < 1e-4f) {
        coef = 1.0f / 12.0f;
    } else {
        float s, c;
        sincosf(theta, &s, &c);
        coef = 1.0f / theta2 - (1.0f + c) / (2.0f * theta * s);
    }
    V3 pxt = vcross(phi, t);
    *tau = vadd(vsub(t, vscale(pxt, 0.5f)), vscale(vcross(phi, pxt), coef));
    *phi_out = phi;
}

// --- Vectorized 7-float row fetch for CONTIGUOUS streams: 3 aligned float4 (3rd predicated) ---
struct Row12 { float4 r0, r1, r2; int off; };

__device__ __forceinline__ Row12 fetch_row_vec(const float4* __restrict__ p4, size_t row_idx) {
    Row12 r;
    size_t base = row_idx * 7;
    size_t a = base >> 2;
    r.off = (int)(base & 3);
    r.r0 = __ldcs(p4 + a);
    r.r1 = __ldcs(p4 + a + 1);
    r.r2 = (r.off >= 2) ? __ldcs(p4 + a + 2) : r.r1;
    return r;
}

__device__ __forceinline__ void extract7(const Row12& rr, V3* t, Q4* q) {
    float s0=rr.r0.x, s1=rr.r0.y, s2=rr.r0.z, s3=rr.r0.w;
    float s4=rr.r1.x, s5=rr.r1.y, s6=rr.r1.z, s7=rr.r1.w;
    float s8=rr.r2.x, s9=rr.r2.y;
    bool o2 = (rr.off & 2) != 0;
    bool o1 = (rr.off & 1) != 0;
    float u0 = o2 ? s2 : s0;
    float u1 = o2 ? s3 : s1;
    float u2 = o2 ? s4 : s2;
    float u3 = o2 ? s5 : s3;
    float u4 = o2 ? s6 : s4;
    float u5 = o2 ? s7 : s5;
    float u6 = o2 ? s8 : s6;
    float u7 = o2 ? s9 : s7;
    float v0 = o1 ? u1 : u0;
    float v1 = o1 ? u2 : u1;
    float v2 = o1 ? u3 : u2;
    float v3f = o1 ? u4 : u3;
    float v4 = o1 ? u5 : u4;
    float v5 = o1 ? u6 : u5;
    float v6 = o1 ? u7 : u6;
    t->x = v0; t->y = v1; t->z = v2;
    q->x = v3f; q->y = v4; q->z = v5; q->w = v6;
}

__device__ __forceinline__ void fetch_row_scalar(const float* __restrict__ p, size_t row_idx,
                                                 V3* t, Q4* q) {
    const float* r = p + row_idx * 7;
    t->x = __ldcs(r+0); t->y = __ldcs(r+1); t->z = __ldcs(r+2);
    q->x = __ldcs(r+3); q->y = __ldcs(r+4); q->z = __ldcs(r+5); q->w = __ldcs(r+6);
}

// --- 256-bit single-instruction row gather (sm_100+: ld.global.nc.v8.b32) ---
__device__ __forceinline__ void load_row8_v8(size_t i, V3* t, Q4* q) {
    const float4* p = &g_nodes8[2 * i];
    unsigned r0, r1, r2, r3, r4, r5, r6, r7;
    asm volatile("ld.global.nc.v8.b32 {%0,%1,%2,%3,%4,%5,%6,%7}, [%8];"
                 : "=r"(r0), "=r"(r1), "=r"(r2), "=r"(r3),
                   "=r"(r4), "=r"(r5), "=r"(r6), "=r"(r7)
                 : "l"(p));
    t->x = __uint_as_float(r0);
    t->y = __uint_as_float(r1);
    t->z = __uint_as_float(r2);
    q->x = __uint_as_float(r3);
    q->y = __uint_as_float(r4);
    q->z = __uint_as_float(r5);
    q->w = __uint_as_float(r6);
}

// --- Prep kernel: repack nodes into scratch AND compute node residuals ---
template<bool VEC>
__global__ __launch_bounds__(256)
void prep_kernel(const float* __restrict__ nodes,
                 const float* __restrict__ vels,
                 const float* __restrict__ imu_drots,
                 const float* __restrict__ imu_dtrans,
                 const float* __restrict__ imu_dvels,
                 const float* __restrict__ dts,
                 float* __restrict__ out_adjvel,
                 float* __restrict__ out_imurot,
                 float* __restrict__ out_transvel,
                 int N, int M)
{
    int i = blockIdx.x * blockDim.x + threadIdx.x;
    int lane = threadIdx.x & 31;
    bool v_row = i < N;
    int ic = v_row ? i : (N - 1);

    V3 t0; Q4 q0;
    if (VEC) {
        Row12 r = fetch_row_vec(reinterpret_cast<const float4*>(nodes), (size_t)ic);
        extract7(r, &t0, &q0);
    } else {
        fetch_row_scalar(nodes, (size_t)ic, &t0, &q0);
    }

    if (v_row) {
        g_nodes8[2*(size_t)i]     = make_float4(t0.x, t0.y, t0.z, q0.x);
        g_nodes8[2*(size_t)i + 1] = make_float4(q0.y, q0.z, q0.w, 0.0f);
    }

    float v0x = __ldcs(vels + 3*(size_t)ic + 0);
    float v0y = __ldcs(vels + 3*(size_t)ic + 1);
    float v0z = __ldcs(vels + 3*(size_t)ic + 2);

    unsigned mask = 0xffffffffu;
    V3 t1; Q4 q1;
    t1.x = __shfl_down_sync(mask, t0.x, 1);
    t1.y = __shfl_down_sync(mask, t0.y, 1);
    t1.z = __shfl_down_sync(mask, t0.z, 1);
    q1.x = __shfl_down_sync(mask, q0.x, 1);
    q1.y = __shfl_down_sync(mask, q0.y, 1);
    q1.z = __shfl_down_sync(mask, q0.z, 1);
    q1.w = __shfl_down_sync(mask, q0.w, 1);
    float v1x = __shfl_down_sync(mask, v0x, 1);
    float v1y = __shfl_down_sync(mask, v0y, 1);
    float v1z = __shfl_down_sync(mask, v0z, 1);

    if (i >= M) return;

    if (lane == 31) {
        if (VEC) {
            Row12 r = fetch_row_vec(reinterpret_cast<const float4*>(nodes), (size_t)(i+1));
            extract7(r, &t1, &q1);
        } else {
            fetch_row_scalar(nodes, (size_t)(i+1), &t1, &q1);
        }
        v1x = __ldcs(vels + 3*(size_t)(i+1) + 0);
        v1y = __ldcs(vels + 3*(size_t)(i+1) + 1);
        v1z = __ldcs(vels + 3*(size_t)(i+1) + 2);
    }

    float4 drq = __ldcs(reinterpret_cast<const float4*>(imu_drots) + i);
    float dvx = __ldcs(imu_dvels + 3*(size_t)i + 0);
    float dvy = __ldcs(imu_dvels + 3*(size_t)i + 1);
    float dvz = __ldcs(imu_dvels + 3*(size_t)i + 2);
    float dtx = __ldcs(imu_dtrans + 3*(size_t)i + 0);
    float dty = __ldcs(imu_dtrans + 3*(size_t)i + 1);
    float dtz = __ldcs(imu_dtrans + 3*(size_t)i + 2);
    float dt  = __ldcs(dts + i);

    __stcs(out_adjvel + 3*(size_t)i + 0, 0.1f * (dvx - (v1x - v0x)));
    __stcs(out_adjvel + 3*(size_t)i + 1, 0.1f * (dvy - (v1y - v0y)));
    __stcs(out_adjvel + 3*(size_t)i + 2, 0.1f * (dvz - (v1z - v0z)));

    Q4 dr; dr.x=drq.x; dr.y=drq.y; dr.z=drq.z; dr.w=drq.w;
    Q4 qre = qmul(qconj(dr), qmul(qconj(q0), q1));
    V3 rot = so3_log(qre);
    __stcs(out_imurot + 3*(size_t)i + 0, rot.x);
    __stcs(out_imurot + 3*(size_t)i + 1, rot.y);
    __stcs(out_imurot + 3*(size_t)i + 2, rot.z);

    __stcs(out_transvel + 3*(size_t)i + 0, 0.1f * (t1.x - t0.x - fmaf(v0x, dt, dtx)));
    __stcs(out_transvel + 3*(size_t)i + 1, 0.1f * (t1.y - t0.y - fmaf(v0y, dt, dty)));
    __stcs(out_transvel + 3*(size_t)i + 2, 0.1f * (t1.z - t0.z - fmaf(v0z, dt, dtz)));
}

__device__ __forceinline__ void edge_math_store(V3 t1, Q4 q1, V3 t2, Q4 q2,
                                                V3 tp, Q4 qp,
                                                float* __restrict__ out_pg, size_t e)
{
    Q4 qi1 = qconj(q1);
    V3 ti1 = vscale(qrot(qi1, t1), -1.0f);
    Q4 qa  = qmul(qi1, q2);
    V3 ta  = vadd(ti1, qrot(qi1, t2));

    Q4 qip = qconj(qp);
    V3 tip = vscale(qrot(qip, tp), -1.0f);
    Q4 qe  = qmul(qip, qa);
    V3 te  = vadd(tip, qrot(qip, ta));

    V3 tau, phi;
    se3_log(te, qe, &tau, &phi);

    float2* o2 = reinterpret_cast<float2*>(out_pg + 6*e);
    __stcs(o2 + 0, make_float2(tau.x, tau.y));
    __stcs(o2 + 1, make_float2(tau.z, phi.x));
    __stcs(o2 + 2, make_float2(phi.y, phi.z));
}

// --- Edge kernel: 2 edges per thread (e, e+TPB) for doubled MLP ---
template<bool VEC>
__global__ __launch_bounds__(256)
void edge_kernel(const int*   __restrict__ edges,
                 const float* __restrict__ poses,
                 float* __restrict__ out_pg,
                 int E)
{
    const int TPB = 256;
    int base = blockIdx.x * (2 * TPB);
    int eA = base + threadIdx.x;
    int eB = eA + TPB;
    if (eA >= E) return;
    bool hasB = eB < E;

    // Issue ALL loads for both edges up front.
    int2 idA = __ldcs(reinterpret_cast<const int2*>(edges) + eA);
    int2 idB = hasB ? __ldcs(reinterpret_cast<const int2*>(edges) + eB) : idA;

    V3 tA1, tA2, tB1, tB2;
    Q4 qA1, qA2, qB1, qB2;
    load_row8_v8((size_t)idA.x, &tA1, &qA1);
    load_row8_v8((size_t)idA.y, &tA2, &qA2);
    load_row8_v8((size_t)idB.x, &tB1, &qB1);
    load_row8_v8((size_t)idB.y, &tB2, &qB2);

    V3 tpA, tpB; Q4 qpA, qpB;
    if (VEC) {
        const float4* p4 = reinterpret_cast<const float4*>(poses);
        Row12 rpA = fetch_row_vec(p4, (size_t)eA);
        Row12 rpB = fetch_row_vec(p4, (size_t)(hasB ? eB : eA));
        extract7(rpA, &tpA, &qpA);
        extract7(rpB, &tpB, &qpB);
    } else {
        fetch_row_scalar(poses, (size_t)eA, &tpA, &qpA);
        fetch_row_scalar(poses, (size_t)(hasB ? eB : eA), &tpB, &qpB);
    }

    edge_math_store(tA1, qA1, tA2, qA2, tpA, qpA, out_pg, (size_t)eA);
    if (hasB)
        edge_math_store(tB1, qB1, tB2, qB2, tpB, qpB, out_pg, (size_t)eB);
}

// --- Fallback: edge path reading nodes directly (N > MAX_NODES) ---
__global__ __launch_bounds__(256)
void edge_fallback_kernel(const int*   __restrict__ edges,
                          const float* __restrict__ nodes,
                          const float* __restrict__ poses,
                          float* __restrict__ out_pg,
                          int E)
{
    int e = blockIdx.x * blockDim.x + threadIdx.x;
    if (e >= E) return;
    int2 id = __ldcs(reinterpret_cast<const int2*>(edges) + e);
    V3 t1, t2, tp; Q4 q1, q2, qp;
    fetch_row_scalar(nodes, (size_t)id.x, &t1, &q1);
    fetch_row_scalar(nodes, (size_t)id.y, &t2, &q2);
    fetch_row_scalar(poses, (size_t)e,    &tp, &qp);
    edge_math_store(t1, q1, t2, q2, tp, qp, out_pg, (size_t)e);
}

extern "C" void kernel_launch(void* const* d_in, const int* in_sizes, int n_in,
                              void* d_out, int out_size) {
    const int*   edges      = (const int*)  d_in[0];
    const float* nodes      = (const float*)d_in[1];
    const float* vels       = (const float*)d_in[2];
    const float* poses      = (const float*)d_in[3];
    const float* imu_drots  = (const float*)d_in[4];
    const float* imu_dtrans = (const float*)d_in[5];
    const float* imu_dvels  = (const float*)d_in[6];
    const float* dts        = (const float*)d_in[7];

    int E = in_sizes[0] / 2;
    int N = in_sizes[1] / 7;
    int M = N - 1;

    float* out = (float*)d_out;
    float* out_pg       = out;
    float* out_adjvel   = out + (size_t)6 * E;
    float* out_imurot   = out_adjvel + (size_t)3 * M;
    float* out_transvel = out_imurot + (size_t)3 * M;

    const int TPB = 256;
    int prepBlocks = (N + TPB - 1) / TPB;
    int edgeBlocks = (E + 2*TPB - 1) / (2*TPB);

    bool nodes_vec_ok = ((in_sizes[1] & 3) == 0);
    bool poses_vec_ok = ((in_sizes[3] & 3) == 0);
    bool scr_ok = (N <= MAX_NODES);

    if (scr_ok) {
        if (nodes_vec_ok) {
            prep_kernel<true><<<prepBlocks, TPB>>>(nodes, vels, imu_drots, imu_dtrans,
                                                   imu_dvels, dts,
                                                   out_adjvel, out_imurot, out_transvel, N, M);
        } else {
            prep_kernel<false><<<prepBlocks, TPB>>>(nodes, vels, imu_drots, imu_dtrans,
                                                    imu_dvels, dts,
                                                    out_adjvel, out_imurot, out_transvel, N, M);
        }
        if (poses_vec_ok) {
            edge_kernel<true><<<edgeBlocks, TPB>>>(edges, poses, out_pg, E);
        } else {
            edge_kernel<false><<<edgeBlocks, TPB>>>(edges, poses, out_pg, E);
        }
    } else {
        prep_kernel<false><<<prepBlocks, TPB>>>(nodes, vels, imu_drots, imu_dtrans,
                                                imu_dvels, dts,
                                                out_adjvel, out_imurot, out_transvel,
                                                0, M);
        int fbBlocks = (E + TPB - 1) / TPB;
        edge_fallback_kernel<<<fbBlocks, TPB>>>(edges, nodes, poses, out_pg, E);
    }
}

// round 10
// speedup vs baseline: 1.0975x; 1.0265x over previous
#include <cuda_runtime.h>
#include <math.h>

#define EPS 1e-8f
#define MAX_NODES 1048576

// 32MB padded node scratch: row i -> g_nodes8[2i] = {t.x,t.y,t.z,q.x}, g_nodes8[2i+1] = {q.y,q.z,q.w,pad}
__device__ __align__(32) float4 g_nodes8[(size_t)MAX_NODES * 2];

struct V3 { float x, y, z; };
struct Q4 { float x, y, z, w; };

__device__ __forceinline__ V3 v3(float x, float y, float z) { V3 r; r.x=x; r.y=y; r.z=z; return r; }
__device__ __forceinline__ V3 vadd(V3 a, V3 b) { return v3(a.x+b.x, a.y+b.y, a.z+b.z); }
__device__ __forceinline__ V3 vsub(V3 a, V3 b) { return v3(a.x-b.x, a.y-b.y, a.z-b.z); }
__device__ __forceinline__ V3 vscale(V3 a, float s) { return v3(a.x*s, a.y*s, a.z*s); }
__device__ __forceinline__ float vdot(V3 a, V3 b) { return fmaf(a.x,b.x, fmaf(a.y,b.y, a.z*b.z)); }
__device__ __forceinline__ V3 vcross(V3 a, V3 b) {
    return v3(a.y*b.z - a.z*b.y,
              a.z*b.x - a.x*b.z,
              a.x*b.y - a.y*b.x);
}

__device__ __forceinline__ Q4 qconj(Q4 q) { Q4 r; r.x=-q.x; r.y=-q.y; r.z=-q.z; r.w=q.w; return r; }

__device__ __forceinline__ Q4 qmul(Q4 q, Q4 r) {
    Q4 o;
    V3 qv = v3(q.x,q.y,q.z), rv = v3(r.x,r.y,r.z);
    V3 c = vcross(qv, rv);
    o.x = q.w*r.x + r.w*q.x + c.x;
    o.y = q.w*r.y + r.w*q.y + c.y;
    o.z = q.w*r.z + r.w*q.z + c.z;
    o.w = q.w*r.w - vdot(qv, rv);
    return o;
}

__device__ __forceinline__ V3 qrot(Q4 q, V3 v) {
    V3 qv = v3(q.x,q.y,q.z);
    V3 t = vscale(vcross(qv, v), 2.0f);
    return vadd(vadd(v, vscale(t, q.w)), vcross(qv, t));
}

__device__ __forceinline__ V3 so3_log(Q4 q) {
    V3 v = v3(q.x,q.y,q.z);
    float n2 = vdot(v, v);
    float n = sqrtf(n2);
    float theta = 2.0f * atan2f(n, q.w);
    float k;
    if (n > EPS) {
        k = theta / n;
    } else {
        float wd = (fabsf(q.w) > EPS) ? q.w : 1.0f;
        k = 2.0f / wd;
    }
    return vscale(v, k);
}

__device__ __forceinline__ void se3_log(V3 t, Q4 q, V3* tau, V3* phi_out) {
    V3 phi = so3_log(q);
    float theta2 = vdot(phi, phi);
    float theta = sqrtf(theta2);
    float coef;
    if (theta < 1e-4f) {
        coef = 1.0f / 12.0f;
    } else {
        float s, c;
        sincosf(theta, &s, &c);
        coef = 1.0f / theta2 - (1.0f + c) / (2.0f * theta * s);
    }
    V3 pxt = vcross(phi, t);
    *tau = vadd(vsub(t, vscale(pxt, 0.5f)), vscale(vcross(phi, pxt), coef));
    *phi_out = phi;
}

// --- Vectorized 7-float row fetch for CONTIGUOUS streams: 3 aligned float4 (3rd predicated) ---
struct Row12 { float4 r0, r1, r2; int off; };

__device__ __forceinline__ Row12 fetch_row_vec(const float4* __restrict__ p4, size_t row_idx) {
    Row12 r;
    size_t base = row_idx * 7;
    size_t a = base >> 2;
    r.off = (int)(base & 3);
    r.r0 = __ldcs(p4 + a);
    r.r1 = __ldcs(p4 + a + 1);
    r.r2 = (r.off >= 2) ? __ldcs(p4 + a + 2) : r.r1;
    return r;
}

__device__ __forceinline__ void extract7(const Row12& rr, V3* t, Q4* q) {
    float s0=rr.r0.x, s1=rr.r0.y, s2=rr.r0.z, s3=rr.r0.w;
    float s4=rr.r1.x, s5=rr.r1.y, s6=rr.r1.z, s7=rr.r1.w;
    float s8=rr.r2.x, s9=rr.r2.y;
    bool o2 = (rr.off & 2) != 0;
    bool o1 = (rr.off & 1) != 0;
    float u0 = o2 ? s2 : s0;
    float u1 = o2 ? s3 : s1;
    float u2 = o2 ? s4 : s2;
    float u3 = o2 ? s5 : s3;
    float u4 = o2 ? s6 : s4;
    float u5 = o2 ? s7 : s5;
    float u6 = o2 ? s8 : s6;
    float u7 = o2 ? s9 : s7;
    float v0 = o1 ? u1 : u0;
    float v1 = o1 ? u2 : u1;
    float v2 = o1 ? u3 : u2;
    float v3f = o1 ? u4 : u3;
    float v4 = o1 ? u5 : u4;
    float v5 = o1 ? u6 : u5;
    float v6 = o1 ? u7 : u6;
    t->x = v0; t->y = v1; t->z = v2;
    q->x = v3f; q->y = v4; q->z = v5; q->w = v6;
}

__device__ __forceinline__ void fetch_row_scalar(const float* __restrict__ p, size_t row_idx,
                                                 V3* t, Q4* q) {
    const float* r = p + row_idx * 7;
    t->x = __ldcs(r+0); t->y = __ldcs(r+1); t->z = __ldcs(r+2);
    q->x = __ldcs(r+3); q->y = __ldcs(r+4); q->z = __ldcs(r+5); q->w = __ldcs(r+6);
}

// --- 256-bit single-instruction row load (sm_100+: ld.global.nc.v8.b32) ---
__device__ __forceinline__ void load_row8_v8(size_t i, V3* t, Q4* q) {
    const float4* p = &g_nodes8[2 * i];
    unsigned r0, r1, r2, r3, r4, r5, r6, r7;
    asm volatile("ld.global.nc.v8.b32 {%0,%1,%2,%3,%4,%5,%6,%7}, [%8];"
                 : "=r"(r0), "=r"(r1), "=r"(r2), "=r"(r3),
                   "=r"(r4), "=r"(r5), "=r"(r6), "=r"(r7)
                 : "l"(p));
    t->x = __uint_as_float(r0);
    t->y = __uint_as_float(r1);
    t->z = __uint_as_float(r2);
    q->x = __uint_as_float(r3);
    q->y = __uint_as_float(r4);
    q->z = __uint_as_float(r5);
    q->w = __uint_as_float(r6);
}

// --- Repack kernel: nodes (7 floats/row) -> scratch (8 floats/row, 32B aligned) ---
template<bool VEC>
__global__ __launch_bounds__(256)
void repack_kernel(const float* __restrict__ nodes, int N)
{
    int i = blockIdx.x * blockDim.x + threadIdx.x;
    if (i >= N) return;
    V3 t; Q4 q;
    if (VEC) {
        Row12 r = fetch_row_vec(reinterpret_cast<const float4*>(nodes), (size_t)i);
        extract7(r, &t, &q);
    } else {
        fetch_row_scalar(nodes, (size_t)i, &t, &q);
    }
    g_nodes8[2*(size_t)i]     = make_float4(t.x, t.y, t.z, q.x);
    g_nodes8[2*(size_t)i + 1] = make_float4(q.y, q.z, q.w, 0.0f);
}

__device__ __forceinline__ void edge_math_store(V3 t1, Q4 q1, V3 t2, Q4 q2,
                                                V3 tp, Q4 qp,
                                                float* __restrict__ out_pg, size_t e)
{
    Q4 qi1 = qconj(q1);
    V3 ti1 = vscale(qrot(qi1, t1), -1.0f);
    Q4 qa  = qmul(qi1, q2);
    V3 ta  = vadd(ti1, qrot(qi1, t2));

    Q4 qip = qconj(qp);
    V3 tip = vscale(qrot(qip, tp), -1.0f);
    Q4 qe  = qmul(qip, qa);
    V3 te  = vadd(tip, qrot(qip, ta));

    V3 tau, phi;
    se3_log(te, qe, &tau, &phi);

    float2* o2 = reinterpret_cast<float2*>(out_pg + 6*e);
    __stcs(o2 + 0, make_float2(tau.x, tau.y));
    __stcs(o2 + 1, make_float2(tau.z, phi.x));
    __stcs(o2 + 2, make_float2(phi.y, phi.z));
}

// --- Fused kernel: edge blocks + node blocks, interleaved by block index ---
// Block mapping (requires edgeB >= nodeB): odd blocks b with (b>>1) < nodeB are
// node blocks (index b>>1); all others are edge blocks (index b - min(b>>1, nodeB)).
template<bool VEC>
__global__ __launch_bounds__(256)
void fused_kernel(const int*   __restrict__ edges,
                  const float* __restrict__ poses,
                  const float* __restrict__ vels,
                  const float* __restrict__ imu_drots,
                  const float* __restrict__ imu_dtrans,
                  const float* __restrict__ imu_dvels,
                  const float* __restrict__ dts,
                  float* __restrict__ out_pg,
                  float* __restrict__ out_adjvel,
                  float* __restrict__ out_imurot,
                  float* __restrict__ out_transvel,
                  int E, int M, int nodeB)
{
    int b = blockIdx.x;
    int half = b >> 1;
    bool isNode = (b & 1) && (half < nodeB);

    if (!isNode) {
        // ---- edge path: 1 edge per thread, v8 gathers ----
        int eb = b - min(half, nodeB);
        int e = eb * blockDim.x + threadIdx.x;
        if (e >= E) return;

        int2 id = __ldcs(reinterpret_cast<const int2*>(edges) + e);

        V3 t1, t2, tp;
        Q4 q1, q2, qp;
        load_row8_v8((size_t)id.x, &t1, &q1);
        load_row8_v8((size_t)id.y, &t2, &q2);

        if (VEC) {
            Row12 rp = fetch_row_vec(reinterpret_cast<const float4*>(poses), (size_t)e);
            extract7(rp, &tp, &qp);
        } else {
            fetch_row_scalar(poses, (size_t)e, &tp, &qp);
        }

        edge_math_store(t1, q1, t2, q2, tp, qp, out_pg, (size_t)e);
    } else {
        // ---- node path: reads repacked scratch with coalesced v8 loads ----
        int i = half * blockDim.x + threadIdx.x;
        if (i >= M) return;

        V3 t0, t1; Q4 q0, q1;
        load_row8_v8((size_t)i,     &t0, &q0);
        load_row8_v8((size_t)i + 1, &t1, &q1);

        float v0x = __ldcs(vels + 3*(size_t)i + 0);
        float v0y = __ldcs(vels + 3*(size_t)i + 1);
        float v0z = __ldcs(vels + 3*(size_t)i + 2);
        float v1x = __ldcs(vels + 3*(size_t)i + 3);
        float v1y = __ldcs(vels + 3*(size_t)i + 4);
        float v1z = __ldcs(vels + 3*(size_t)i + 5);

        float4 drq = __ldcs(reinterpret_cast<const float4*>(imu_drots) + i);
        float dvx = __ldcs(imu_dvels + 3*(size_t)i + 0);
        float dvy = __ldcs(imu_dvels + 3*(size_t)i + 1);
        float dvz = __ldcs(imu_dvels + 3*(size_t)i + 2);
        float dtx = __ldcs(imu_dtrans + 3*(size_t)i + 0);
        float dty = __ldcs(imu_dtrans + 3*(size_t)i + 1);
        float dtz = __ldcs(imu_dtrans + 3*(size_t)i + 2);
        float dt  = __ldcs(dts + i);

        __stcs(out_adjvel + 3*(size_t)i + 0, 0.1f * (dvx - (v1x - v0x)));
        __stcs(out_adjvel + 3*(size_t)i + 1, 0.1f * (dvy - (v1y - v0y)));
        __stcs(out_adjvel + 3*(size_t)i + 2, 0.1f * (dvz - (v1z - v0z)));

        Q4 dr; dr.x=drq.x; dr.y=drq.y; dr.z=drq.z; dr.w=drq.w;
        Q4 qre = qmul(qconj(dr), qmul(qconj(q0), q1));
        V3 rot = so3_log(qre);
        __stcs(out_imurot + 3*(size_t)i + 0, rot.x);
        __stcs(out_imurot + 3*(size_t)i + 1, rot.y);
        __stcs(out_imurot + 3*(size_t)i + 2, rot.z);

        __stcs(out_transvel + 3*(size_t)i + 0, 0.1f * (t1.x - t0.x - fmaf(v0x, dt, dtx)));
        __stcs(out_transvel + 3*(size_t)i + 1, 0.1f * (t1.y - t0.y - fmaf(v0y, dt, dty)));
        __stcs(out_transvel + 3*(size_t)i + 2, 0.1f * (t1.z - t0.z - fmaf(v0z, dt, dtz)));
    }
}

// --- Fallback path (N > MAX_NODES): direct reads, two simple kernels ---
__global__ __launch_bounds__(256)
void edge_fallback_kernel(const int*   __restrict__ edges,
                          const float* __restrict__ nodes,
                          const float* __restrict__ poses,
                          float* __restrict__ out_pg,
                          int E)
{
    int e = blockIdx.x * blockDim.x + threadIdx.x;
    if (e >= E) return;
    int2 id = __ldcs(reinterpret_cast<const int2*>(edges) + e);
    V3 t1, t2, tp; Q4 q1, q2, qp;
    fetch_row_scalar(nodes, (size_t)id.x, &t1, &q1);
    fetch_row_scalar(nodes, (size_t)id.y, &t2, &q2);
    fetch_row_scalar(poses, (size_t)e,    &tp, &qp);
    edge_math_store(t1, q1, t2, q2, tp, qp, out_pg, (size_t)e);
}

__global__ __launch_bounds__(256)
void node_fallback_kernel(const float* __restrict__ nodes,
                          const float* __restrict__ vels,
                          const float* __restrict__ imu_drots,
                          const float* __restrict__ imu_dtrans,
                          const float* __restrict__ imu_dvels,
                          const float* __restrict__ dts,
                          float* __restrict__ out_adjvel,
                          float* __restrict__ out_imurot,
                          float* __restrict__ out_transvel,
                          int M)
{
    int i = blockIdx.x * blockDim.x + threadIdx.x;
    if (i >= M) return;
    V3 t0, t1; Q4 q0, q1;
    fetch_row_scalar(nodes, (size_t)i, &t0, &q0);
    fetch_row_scalar(nodes, (size_t)i + 1, &t1, &q1);

    float v0x=vels[3*(size_t)i+0], v0y=vels[3*(size_t)i+1], v0z=vels[3*(size_t)i+2];
    float v1x=vels[3*(size_t)i+3], v1y=vels[3*(size_t)i+4], v1z=vels[3*(size_t)i+5];
    float4 drq = *reinterpret_cast<const float4*>(imu_drots + 4*(size_t)i);
    float dvx=imu_dvels[3*(size_t)i+0], dvy=imu_dvels[3*(size_t)i+1], dvz=imu_dvels[3*(size_t)i+2];
    float dtx=imu_dtrans[3*(size_t)i+0], dty=imu_dtrans[3*(size_t)i+1], dtz=imu_dtrans[3*(size_t)i+2];
    float dt = dts[i];

    out_adjvel[3*(size_t)i+0] = 0.1f * (dvx - (v1x - v0x));
    out_adjvel[3*(size_t)i+1] = 0.1f * (dvy - (v1y - v0y));
    out_adjvel[3*(size_t)i+2] = 0.1f * (dvz - (v1z - v0z));

    Q4 dr; dr.x=drq.x; dr.y=drq.y; dr.z=drq.z; dr.w=drq.w;
    Q4 qre = qmul(qconj(dr), qmul(qconj(q0), q1));
    V3 rot = so3_log(qre);
    out_imurot[3*(size_t)i+0] = rot.x;
    out_imurot[3*(size_t)i+1] = rot.y;
    out_imurot[3*(size_t)i+2] = rot.z;

    out_transvel[3*(size_t)i+0] = 0.1f * (t1.x - t0.x - fmaf(v0x, dt, dtx));
    out_transvel[3*(size_t)i+1] = 0.1f * (t1.y - t0.y - fmaf(v0y, dt, dty));
    out_transvel[3*(size_t)i+2] = 0.1f * (t1.z - t0.z - fmaf(v0z, dt, dtz));
}

extern "C" void kernel_launch(void* const* d_in, const int* in_sizes, int n_in,
                              void* d_out, int out_size) {
    const int*   edges      = (const int*)  d_in[0];
    const float* nodes      = (const float*)d_in[1];
    const float* vels       = (const float*)d_in[2];
    const float* poses      = (const float*)d_in[3];
    const float* imu_drots  = (const float*)d_in[4];
    const float* imu_dtrans = (const float*)d_in[5];
    const float* imu_dvels  = (const float*)d_in[6];
    const float* dts        = (const float*)d_in[7];

    int E = in_sizes[0] / 2;
    int N = in_sizes[1] / 7;
    int M = N - 1;

    float* out = (float*)d_out;
    float* out_pg       = out;
    float* out_adjvel   = out + (size_t)6 * E;
    float* out_imurot   = out_adjvel + (size_t)3 * M;
    float* out_transvel = out_imurot + (size_t)3 * M;

    const int TPB = 256;
    int edgeB = (E + TPB - 1) / TPB;
    int nodeB = (M + TPB - 1) / TPB;

    bool nodes_vec_ok = ((in_sizes[1] & 3) == 0);
    bool poses_vec_ok = ((in_sizes[3] & 3) == 0);
    bool scr_ok = (N <= MAX_NODES) && (edgeB >= nodeB);

    if (scr_ok) {
        int repB = (N + TPB - 1) / TPB;
        if (nodes_vec_ok) repack_kernel<true><<<repB, TPB>>>(nodes, N);
        else              repack_kernel<false><<<repB, TPB>>>(nodes, N);

        int totB = edgeB + nodeB;
        if (poses_vec_ok) {
            fused_kernel<true><<<totB, TPB>>>(edges, poses, vels, imu_drots, imu_dtrans,
                                              imu_dvels, dts, out_pg, out_adjvel,
                                              out_imurot, out_transvel, E, M, nodeB);
        } else {
            fused_kernel<false><<<totB, TPB>>>(edges, poses, vels, imu_drots, imu_dtrans,
                                               imu_dvels, dts, out_pg, out_adjvel,
                                               out_imurot, out_transvel, E, M, nodeB);
        }
    } else {
        node_fallback_kernel<<<nodeB, TPB>>>(nodes, vels, imu_drots, imu_dtrans,
                                             imu_dvels, dts,
                                             out_adjvel, out_imurot, out_transvel, M);
        edge_fallback_kernel<<<edgeB, TPB>>>(edges, nodes, poses, out_pg, E);
    }
}

// round 11
// speedup vs baseline: 1.1531x; 1.0507x over previous
#include <cuda_runtime.h>
#include <math.h>

#define EPS 1e-8f
#define MAX_NODES 1048576

// 32MB padded node scratch: row i -> g_nodes8[2i] = {t.x,t.y,t.z,q.x}, g_nodes8[2i+1] = {q.y,q.z,q.w,pad}
__device__ __align__(32) float4 g_nodes8[(size_t)MAX_NODES * 2];

struct V3 { float x, y, z; };
struct Q4 { float x, y, z, w; };

__device__ __forceinline__ V3 v3(float x, float y, float z) { V3 r; r.x=x; r.y=y; r.z=z; return r; }
__device__ __forceinline__ V3 vadd(V3 a, V3 b) { return v3(a.x+b.x, a.y+b.y, a.z+b.z); }
__device__ __forceinline__ V3 vsub(V3 a, V3 b) { return v3(a.x-b.x, a.y-b.y, a.z-b.z); }
__device__ __forceinline__ V3 vscale(V3 a, float s) { return v3(a.x*s, a.y*s, a.z*s); }
__device__ __forceinline__ float vdot(V3 a, V3 b) { return fmaf(a.x,b.x, fmaf(a.y,b.y, a.z*b.z)); }
__device__ __forceinline__ V3 vcross(V3 a, V3 b) {
    return v3(a.y*b.z - a.z*b.y,
              a.z*b.x - a.x*b.z,
              a.x*b.y - a.y*b.x);
}

__device__ __forceinline__ Q4 qconj(Q4 q) { Q4 r; r.x=-q.x; r.y=-q.y; r.z=-q.z; r.w=q.w; return r; }

__device__ __forceinline__ Q4 qmul(Q4 q, Q4 r) {
    Q4 o;
    V3 qv = v3(q.x,q.y,q.z), rv = v3(r.x,r.y,r.z);
    V3 c = vcross(qv, rv);
    o.x = q.w*r.x + r.w*q.x + c.x;
    o.y = q.w*r.y + r.w*q.y + c.y;
    o.z = q.w*r.z + r.w*q.z + c.z;
    o.w = q.w*r.w - vdot(qv, rv);
    return o;
}

__device__ __forceinline__ V3 qrot(Q4 q, V3 v) {
    V3 qv = v3(q.x,q.y,q.z);
    V3 t = vscale(vcross(qv, v), 2.0f);
    return vadd(vadd(v, vscale(t, q.w)), vcross(qv, t));
}

__device__ __forceinline__ V3 so3_log(Q4 q) {
    V3 v = v3(q.x,q.y,q.z);
    float n2 = vdot(v, v);
    float n = sqrtf(n2);
    float theta = 2.0f * atan2f(n, q.w);
    float k;
    if (n > EPS) {
        k = theta / n;
    } else {
        float wd = (fabsf(q.w) > EPS) ? q.w : 1.0f;
        k = 2.0f / wd;
    }
    return vscale(v, k);
}

__device__ __forceinline__ void se3_log(V3 t, Q4 q, V3* tau, V3* phi_out) {
    V3 phi = so3_log(q);
    float theta2 = vdot(phi, phi);
    float theta = sqrtf(theta2);
    float coef;
    if (theta < 1e-4f) {
        coef = 1.0f / 12.0f;
    } else {
        float s, c;
        sincosf(theta, &s, &c);
        coef = 1.0f / theta2 - (1.0f + c) / (2.0f * theta * s);
    }
    V3 pxt = vcross(phi, t);
    *tau = vadd(vsub(t, vscale(pxt, 0.5f)), vscale(vcross(phi, pxt), coef));
    *phi_out = phi;
}

// --- Vectorized 7-float row fetch for CONTIGUOUS streams: 3 aligned float4 (3rd predicated) ---
struct Row12 { float4 r0, r1, r2; int off; };

__device__ __forceinline__ Row12 fetch_row_vec(const float4* __restrict__ p4, size_t row_idx) {
    Row12 r;
    size_t base = row_idx * 7;
    size_t a = base >> 2;
    r.off = (int)(base & 3);
    r.r0 = __ldcs(p4 + a);
    r.r1 = __ldcs(p4 + a + 1);
    r.r2 = (r.off >= 2) ? __ldcs(p4 + a + 2) : r.r1;
    return r;
}

__device__ __forceinline__ void extract7(const Row12& rr, V3* t, Q4* q) {
    float s0=rr.r0.x, s1=rr.r0.y, s2=rr.r0.z, s3=rr.r0.w;
    float s4=rr.r1.x, s5=rr.r1.y, s6=rr.r1.z, s7=rr.r1.w;
    float s8=rr.r2.x, s9=rr.r2.y;
    bool o2 = (rr.off & 2) != 0;
    bool o1 = (rr.off & 1) != 0;
    float u0 = o2 ? s2 : s0;
    float u1 = o2 ? s3 : s1;
    float u2 = o2 ? s4 : s2;
    float u3 = o2 ? s5 : s3;
    float u4 = o2 ? s6 : s4;
    float u5 = o2 ? s7 : s5;
    float u6 = o2 ? s8 : s6;
    float u7 = o2 ? s9 : s7;
    float v0 = o1 ? u1 : u0;
    float v1 = o1 ? u2 : u1;
    float v2 = o1 ? u3 : u2;
    float v3f = o1 ? u4 : u3;
    float v4 = o1 ? u5 : u4;
    float v5 = o1 ? u6 : u5;
    float v6 = o1 ? u7 : u6;
    t->x = v0; t->y = v1; t->z = v2;
    q->x = v3f; q->y = v4; q->z = v5; q->w = v6;
}

__device__ __forceinline__ void fetch_row_scalar(const float* __restrict__ p, size_t row_idx,
                                                 V3* t, Q4* q) {
    const float* r = p + row_idx * 7;
    t->x = __ldcs(r+0); t->y = __ldcs(r+1); t->z = __ldcs(r+2);
    q->x = __ldcs(r+3); q->y = __ldcs(r+4); q->z = __ldcs(r+5); q->w = __ldcs(r+6);
}

// --- 256-bit single-instruction row load (sm_100+: ld.global.nc.v8.b32) ---
__device__ __forceinline__ void load_row8_v8(size_t i, V3* t, Q4* q) {
    const float4* p = &g_nodes8[2 * i];
    unsigned r0, r1, r2, r3, r4, r5, r6, r7;
    asm volatile("ld.global.nc.v8.b32 {%0,%1,%2,%3,%4,%5,%6,%7}, [%8];"
                 : "=r"(r0), "=r"(r1), "=r"(r2), "=r"(r3),
                   "=r"(r4), "=r"(r5), "=r"(r6), "=r"(r7)
                 : "l"(p));
    t->x = __uint_as_float(r0);
    t->y = __uint_as_float(r1);
    t->z = __uint_as_float(r2);
    q->x = __uint_as_float(r3);
    q->y = __uint_as_float(r4);
    q->z = __uint_as_float(r5);
    q->w = __uint_as_float(r6);
}

// 256-bit scratch row store
__device__ __forceinline__ void store_row8_v8(size_t i, V3 t, Q4 q) {
    float4* p = &g_nodes8[2 * i];
    asm volatile("st.global.v8.b32 [%0], {%1,%2,%3,%4,%5,%6,%7,%8};"
                 :: "l"(p),
                    "r"(__float_as_uint(t.x)), "r"(__float_as_uint(t.y)),
                    "r"(__float_as_uint(t.z)), "r"(__float_as_uint(q.x)),
                    "r"(__float_as_uint(q.y)), "r"(__float_as_uint(q.z)),
                    "r"(__float_as_uint(q.w)), "r"(0u)
                 : "memory");
}

// --- Repack kernel: nodes (7 floats/row) -> scratch (8 floats/row, 32B aligned) ---
template<bool VEC>
__global__ __launch_bounds__(256)
void repack_kernel(const float* __restrict__ nodes, int N)
{
    int i = blockIdx.x * blockDim.x + threadIdx.x;
    if (i >= N) return;
    V3 t; Q4 q;
    if (VEC) {
        Row12 r = fetch_row_vec(reinterpret_cast<const float4*>(nodes), (size_t)i);
        extract7(r, &t, &q);
    } else {
        fetch_row_scalar(nodes, (size_t)i, &t, &q);
    }
    store_row8_v8((size_t)i, t, q);
}

__device__ __forceinline__ void edge_math_store(V3 t1, Q4 q1, V3 t2, Q4 q2,
                                                V3 tp, Q4 qp,
                                                float* __restrict__ out_pg, size_t e)
{
    Q4 qi1 = qconj(q1);
    V3 ti1 = vscale(qrot(qi1, t1), -1.0f);
    Q4 qa  = qmul(qi1, q2);
    V3 ta  = vadd(ti1, qrot(qi1, t2));

    Q4 qip = qconj(qp);
    V3 tip = vscale(qrot(qip, tp), -1.0f);
    Q4 qe  = qmul(qip, qa);
    V3 te  = vadd(tip, qrot(qip, ta));

    V3 tau, phi;
    se3_log(te, qe, &tau, &phi);

    float2* o2 = reinterpret_cast<float2*>(out_pg + 6*e);
    __stcs(o2 + 0, make_float2(tau.x, tau.y));
    __stcs(o2 + 1, make_float2(tau.z, phi.x));
    __stcs(o2 + 2, make_float2(phi.y, phi.z));
}

// --- Fused kernel: edge blocks (2 edges/thread) + node blocks, 1:1 interleaved ---
// cmin = min(edgeB2, nodeB). For b < 2*cmin: even -> edge b/2, odd -> node b/2.
// For b >= 2*cmin: the longer list continues with idx = b - cmin.
template<bool VEC>
__global__ __launch_bounds__(256)
void fused_kernel(const int*   __restrict__ edges,
                  const float* __restrict__ poses,
                  const float* __restrict__ vels,
                  const float* __restrict__ imu_drots,
                  const float* __restrict__ imu_dtrans,
                  const float* __restrict__ imu_dvels,
                  const float* __restrict__ dts,
                  float* __restrict__ out_pg,
                  float* __restrict__ out_adjvel,
                  float* __restrict__ out_imurot,
                  float* __restrict__ out_transvel,
                  int E, int M, int edgeB2, int nodeB)
{
    int b = blockIdx.x;
    int cmin = min(edgeB2, nodeB);
    bool isNode;
    int idx;
    if (b < 2 * cmin) {
        isNode = (b & 1);
        idx = b >> 1;
    } else {
        isNode = (nodeB > cmin);
        idx = b - cmin;
    }

    if (!isNode) {
        // ---- edge path: 2 edges per thread (eA, eA+256) ----
        int eA = idx * 512 + threadIdx.x;
        int eB = eA + 256;
        if (eA >= E) return;
        bool hasB = eB < E;

        int2 idA = __ldcs(reinterpret_cast<const int2*>(edges) + eA);
        int2 idB = hasB ? __ldcs(reinterpret_cast<const int2*>(edges) + eB) : idA;

        V3 tA1, tA2, tB1, tB2;
        Q4 qA1, qA2, qB1, qB2;
        load_row8_v8((size_t)idA.x, &tA1, &qA1);
        load_row8_v8((size_t)idA.y, &tA2, &qA2);
        load_row8_v8((size_t)idB.x, &tB1, &qB1);
        load_row8_v8((size_t)idB.y, &tB2, &qB2);

        V3 tpA, tpB; Q4 qpA, qpB;
        if (VEC) {
            const float4* p4 = reinterpret_cast<const float4*>(poses);
            Row12 rpA = fetch_row_vec(p4, (size_t)eA);
            Row12 rpB = fetch_row_vec(p4, (size_t)(hasB ? eB : eA));
            extract7(rpA, &tpA, &qpA);
            extract7(rpB, &tpB, &qpB);
        } else {
            fetch_row_scalar(poses, (size_t)eA, &tpA, &qpA);
            fetch_row_scalar(poses, (size_t)(hasB ? eB : eA), &tpB, &qpB);
        }

        edge_math_store(tA1, qA1, tA2, qA2, tpA, qpA, out_pg, (size_t)eA);
        if (hasB)
            edge_math_store(tB1, qB1, tB2, qB2, tpB, qpB, out_pg, (size_t)eB);
    } else {
        // ---- node path: reads repacked scratch with coalesced v8 loads ----
        int i = idx * blockDim.x + threadIdx.x;
        if (i >= M) return;

        V3 t0, t1; Q4 q0, q1;
        load_row8_v8((size_t)i,     &t0, &q0);
        load_row8_v8((size_t)i + 1, &t1, &q1);

        float v0x = __ldcs(vels + 3*(size_t)i + 0);
        float v0y = __ldcs(vels + 3*(size_t)i + 1);
        float v0z = __ldcs(vels + 3*(size_t)i + 2);
        float v1x = __ldcs(vels + 3*(size_t)i + 3);
        float v1y = __ldcs(vels + 3*(size_t)i + 4);
        float v1z = __ldcs(vels + 3*(size_t)i + 5);

        float4 drq = __ldcs(reinterpret_cast<const float4*>(imu_drots) + i);
        float dvx = __ldcs(imu_dvels + 3*(size_t)i + 0);
        float dvy = __ldcs(imu_dvels + 3*(size_t)i + 1);
        float dvz = __ldcs(imu_dvels + 3*(size_t)i + 2);
        float dtx = __ldcs(imu_dtrans + 3*(size_t)i + 0);
        float dty = __ldcs(imu_dtrans + 3*(size_t)i + 1);
        float dtz = __ldcs(imu_dtrans + 3*(size_t)i + 2);
        float dt  = __ldcs(dts + i);

        __stcs(out_adjvel + 3*(size_t)i + 0, 0.1f * (dvx - (v1x - v0x)));
        __stcs(out_adjvel + 3*(size_t)i + 1, 0.1f * (dvy - (v1y - v0y)));
        __stcs(out_adjvel + 3*(size_t)i + 2, 0.1f * (dvz - (v1z - v0z)));

        Q4 dr; dr.x=drq.x; dr.y=drq.y; dr.z=drq.z; dr.w=drq.w;
        Q4 qre = qmul(qconj(dr), qmul(qconj(q0), q1));
        V3 rot = so3_log(qre);
        __stcs(out_imurot + 3*(size_t)i + 0, rot.x);
        __stcs(out_imurot + 3*(size_t)i + 1, rot.y);
        __stcs(out_imurot + 3*(size_t)i + 2, rot.z);

        __stcs(out_transvel + 3*(size_t)i + 0, 0.1f * (t1.x - t0.x - fmaf(v0x, dt, dtx)));
        __stcs(out_transvel + 3*(size_t)i + 1, 0.1f * (t1.y - t0.y - fmaf(v0y, dt, dty)));
        __stcs(out_transvel + 3*(size_t)i + 2, 0.1f * (t1.z - t0.z - fmaf(v0z, dt, dtz)));
    }
}

// --- Fallback path (N > MAX_NODES): direct reads, two simple kernels ---
__global__ __launch_bounds__(256)
void edge_fallback_kernel(const int*   __restrict__ edges,
                          const float* __restrict__ nodes,
                          const float* __restrict__ poses,
                          float* __restrict__ out_pg,
                          int E)
{
    int e = blockIdx.x * blockDim.x + threadIdx.x;
    if (e >= E) return;
    int2 id = __ldcs(reinterpret_cast<const int2*>(edges) + e);
    V3 t1, t2, tp; Q4 q1, q2, qp;
    fetch_row_scalar(nodes, (size_t)id.x, &t1, &q1);
    fetch_row_scalar(nodes, (size_t)id.y, &t2, &q2);
    fetch_row_scalar(poses, (size_t)e,    &tp, &qp);
    edge_math_store(t1, q1, t2, q2, tp, qp, out_pg, (size_t)e);
}

__global__ __launch_bounds__(256)
void node_fallback_kernel(const float* __restrict__ nodes,
                          const float* __restrict__ vels,
                          const float* __restrict__ imu_drots,
                          const float* __restrict__ imu_dtrans,
                          const float* __restrict__ imu_dvels,
                          const float* __restrict__ dts,
                          float* __restrict__ out_adjvel,
                          float* __restrict__ out_imurot,
                          float* __restrict__ out_transvel,
                          int M)
{
    int i = blockIdx.x * blockDim.x + threadIdx.x;
    if (i >= M) return;
    V3 t0, t1; Q4 q0, q1;
    fetch_row_scalar(nodes, (size_t)i, &t0, &q0);
    fetch_row_scalar(nodes, (size_t)i + 1, &t1, &q1);

    float v0x=vels[3*(size_t)i+0], v0y=vels[3*(size_t)i+1], v0z=vels[3*(size_t)i+2];
    float v1x=vels[3*(size_t)i+3], v1y=vels[3*(size_t)i+4], v1z=vels[3*(size_t)i+5];
    float4 drq = *reinterpret_cast<const float4*>(imu_drots + 4*(size_t)i);
    float dvx=imu_dvels[3*(size_t)i+0], dvy=imu_dvels[3*(size_t)i+1], dvz=imu_dvels[3*(size_t)i+2];
    float dtx=imu_dtrans[3*(size_t)i+0], dty=imu_dtrans[3*(size_t)i+1], dtz=imu_dtrans[3*(size_t)i+2];
    float dt = dts[i];

    out_adjvel[3*(size_t)i+0] = 0.1f * (dvx - (v1x - v0x));
    out_adjvel[3*(size_t)i+1] = 0.1f * (dvy - (v1y - v0y));
    out_adjvel[3*(size_t)i+2] = 0.1f * (dvz - (v1z - v0z));

    Q4 dr; dr.x=drq.x; dr.y=drq.y; dr.z=drq.z; dr.w=drq.w;
    Q4 qre = qmul(qconj(dr), qmul(qconj(q0), q1));
    V3 rot = so3_log(qre);
    out_imurot[3*(size_t)i+0] = rot.x;
    out_imurot[3*(size_t)i+1] = rot.y;
    out_imurot[3*(size_t)i+2] = rot.z;

    out_transvel[3*(size_t)i+0] = 0.1f * (t1.x - t0.x - fmaf(v0x, dt, dtx));
    out_transvel[3*(size_t)i+1] = 0.1f * (t1.y - t0.y - fmaf(v0y, dt, dty));
    out_transvel[3*(size_t)i+2] = 0.1f * (t1.z - t0.z - fmaf(v0z, dt, dtz));
}

extern "C" void kernel_launch(void* const* d_in, const int* in_sizes, int n_in,
                              void* d_out, int out_size) {
    const int*   edges      = (const int*)  d_in[0];
    const float* nodes      = (const float*)d_in[1];
    const float* vels       = (const float*)d_in[2];
    const float* poses      = (const float*)d_in[3];
    const float* imu_drots  = (const float*)d_in[4];
    const float* imu_dtrans = (const float*)d_in[5];
    const float* imu_dvels  = (const float*)d_in[6];
    const float* dts        = (const float*)d_in[7];

    int E = in_sizes[0] / 2;
    int N = in_sizes[1] / 7;
    int M = N - 1;

    float* out = (float*)d_out;
    float* out_pg       = out;
    float* out_adjvel   = out + (size_t)6 * E;
    float* out_imurot   = out_adjvel + (size_t)3 * M;
    float* out_transvel = out_imurot + (size_t)3 * M;

    const int TPB = 256;
    int edgeB2 = (E + 2*TPB - 1) / (2*TPB);
    int nodeB  = (M + TPB - 1) / TPB;

    bool nodes_vec_ok = ((in_sizes[1] & 3) == 0);
    bool poses_vec_ok = ((in_sizes[3] & 3) == 0);
    bool scr_ok = (N <= MAX_NODES);

    if (scr_ok) {
        int repB = (N + TPB - 1) / TPB;
        if (nodes_vec_ok) repack_kernel<true><<<repB, TPB>>>(nodes, N);
        else              repack_kernel<false><<<repB, TPB>>>(nodes, N);

        int totB = edgeB2 + nodeB;
        if (poses_vec_ok) {
            fused_kernel<true><<<totB, TPB>>>(edges, poses, vels, imu_drots, imu_dtrans,
                                              imu_dvels, dts, out_pg, out_adjvel,
                                              out_imurot, out_transvel, E, M, edgeB2, nodeB);
        } else {
            fused_kernel<false><<<totB, TPB>>>(edges, poses, vels, imu_drots, imu_dtrans,
                                               imu_dvels, dts, out_pg, out_adjvel,
                                               out_imurot, out_transvel, E, M, edgeB2, nodeB);
        }
    } else {
        node_fallback_kernel<<<nodeB, TPB>>>(nodes, vels, imu_drots, imu_dtrans,
                                             imu_dvels, dts,
                                             out_adjvel, out_imurot, out_transvel, M);
        int edgeB = (E + TPB - 1) / TPB;
        edge_fallback_kernel<<<edgeB, TPB>>>(edges, nodes, poses, out_pg, E);
    }
}